// round 1
// baseline (speedup 1.0000x reference)
#include <cuda_runtime.h>
#include <cuda_bf16.h>
#include <cstdint>

// EdgeConvE: out[v,h] = sum_w A[v,w] * relu(S[v,h] + T[w,h] + sum_e E[v,w,e]*We[e,h])
// N=1024, F=32, E_ATTR=8, H=64.
// Strategy: precompute S/T (packed for f32x2 lanes) + transposed A; main kernel is
// FMA-pipe bound, uses packed fma.rn.f32x2 to double fp32 throughput.

#define N_NODES 1024
#define F_NODE  32
#define E_ATTR  8
#define H_OUT   64
#define V_TILE  4

typedef unsigned long long u64;

// ---------- f32x2 helpers ----------
__device__ __forceinline__ u64 pk(float lo, float hi) {
    u64 r; asm("mov.b64 %0, {%1,%2};" : "=l"(r) : "f"(lo), "f"(hi)); return r;
}
__device__ __forceinline__ u64 pk1(float x) {
    u64 r; asm("mov.b64 %0, {%1,%1};" : "=l"(r) : "f"(x)); return r;
}
__device__ __forceinline__ void upk(u64 p, float& lo, float& hi) {
    asm("mov.b64 {%0,%1}, %2;" : "=f"(lo), "=f"(hi) : "l"(p));
}
__device__ __forceinline__ u64 fma2(u64 a, u64 b, u64 c) {
    u64 d; asm("fma.rn.f32x2 %0, %1, %2, %3;" : "=l"(d) : "l"(a), "l"(b), "l"(c)); return d;
}
__device__ __forceinline__ u64 add2(u64 a, u64 b) {
    u64 d; asm("add.rn.f32x2 %0, %1, %2;" : "=l"(d) : "l"(a), "l"(b)); return d;
}

// ---------- scratch (no cudaMalloc allowed) ----------
// S4/T4: [w][hl] float4 = {X[h=hl], X[hl+16], X[hl+32], X[hl+48]}, hl in [0,16)
__device__ float4 g_S4[N_NODES * 16];     // 256 KB (S includes +b)
__device__ float4 g_T4[N_NODES * 16];     // 256 KB
__device__ float4 g_A4[(N_NODES / V_TILE) * N_NODES];  // 4 MB: [vblk][w] = A rows v0..v0+3

// ---------- kernel 1: S[v,h], T[v,h] ----------
__global__ void prep_st(const float* __restrict__ X, const float* __restrict__ W,
                        const float* __restrict__ b) {
    const int v = blockIdx.x;
    const int h = threadIdx.x;  // 64 threads
    __shared__ float xs[F_NODE];
    __shared__ float ss[H_OUT], ts[H_OUT];
    if (h < F_NODE) xs[h] = X[v * F_NODE + h];
    __syncthreads();
    float s = b[h], t = 0.0f;
#pragma unroll
    for (int f = 0; f < F_NODE; f++) {
        float ws = W[f * H_OUT + h];
        float wd = W[(f + F_NODE) * H_OUT + h];
        float x = xs[f];
        s = fmaf(x, ws - wd, s);
        t = fmaf(x, wd, t);
    }
    ss[h] = s; ts[h] = t;
    __syncthreads();
    if (h < 16) {
        float4 sv = make_float4(ss[h], ss[h + 16], ss[h + 32], ss[h + 48]);
        float4 tv = make_float4(ts[h], ts[h + 16], ts[h + 32], ts[h + 48]);
        g_S4[v * 16 + h] = sv;
        g_T4[v * 16 + h] = tv;
    }
}

// ---------- kernel 2: adjacency transpose to float4 per v-block ----------
__global__ void prep_a(const int* __restrict__ A) {
    const int vblk = blockIdx.x;
    const int v0 = vblk * V_TILE;
    for (int w = threadIdx.x; w < N_NODES; w += blockDim.x) {
        float4 a = make_float4((float)A[(v0 + 0) * N_NODES + w],
                               (float)A[(v0 + 1) * N_NODES + w],
                               (float)A[(v0 + 2) * N_NODES + w],
                               (float)A[(v0 + 3) * N_NODES + w]);
        g_A4[vblk * N_NODES + w] = a;
    }
}

// ---------- kernel 3: main fused edge-conv ----------
// Grid: 256 blocks (4 v each), 256 threads (8 warps).
// Lane layout: hl = lane&15 selects the h-group {hl, hl+16, hl+32, hl+48};
// half = lane>>4 selects which of 2 simultaneous w's this lane works on.
// Each warp walks a contiguous range of 128 w's, 2 per iteration.
__global__ void __launch_bounds__(256, 2)
edgeconv_main(const float* __restrict__ E, const float* __restrict__ W,
              float* __restrict__ out) {
    const int vblk = blockIdx.x;
    const int v0 = vblk * V_TILE;
    const int tid = threadIdx.x;
    const int warp = tid >> 5;
    const int lane = tid & 31;
    const int hl = lane & 15;
    const int half = lane >> 4;

    // W_edge pairs, loop-invariant: we[e] for (hl,hl+16) and (hl+32,hl+48)
    u64 wep0[E_ATTR], wep1[E_ATTR];
#pragma unroll
    for (int e = 0; e < E_ATTR; e++) {
        const float* wr = W + (2 * F_NODE + e) * H_OUT;
        wep0[e] = pk(wr[hl], wr[hl + 16]);
        wep1[e] = pk(wr[hl + 32], wr[hl + 48]);
    }
    // S pairs per v
    u64 sp0[V_TILE], sp1[V_TILE];
#pragma unroll
    for (int v = 0; v < V_TILE; v++) {
        float4 s4 = g_S4[(v0 + v) * 16 + hl];
        sp0[v] = pk(s4.x, s4.y);
        sp1[v] = pk(s4.z, s4.w);
    }
    u64 ap0[V_TILE], ap1[V_TILE];
#pragma unroll
    for (int v = 0; v < V_TILE; v++) { ap0[v] = pk(0.f, 0.f); ap1[v] = ap0[v]; }

    const float4* __restrict__ A4 = g_A4 + (size_t)vblk * N_NODES;
    const float4* __restrict__ E4 = reinterpret_cast<const float4*>(E);

    const int wend = warp * 128 + 128;
#pragma unroll 2
    for (int w = warp * 128 + half; w < wend; w += 2) {
        float4 t4 = g_T4[w * 16 + hl];          // L2-resident, coalesced per half
        u64 tp0 = pk(t4.x, t4.y);
        u64 tp1 = pk(t4.z, t4.w);
        float4 a4 = A4[w];                      // broadcast within half-warp
#pragma unroll
        for (int v = 0; v < V_TILE; v++) {
            const float4* ep = E4 + ((size_t)((v0 + v) * N_NODES + w) << 1);
            float4 e0 = ep[0];                  // broadcast LDG.128 (E streamed)
            float4 e1 = ep[1];
            u64 m0 = add2(sp0[v], tp0);
            u64 m1 = add2(sp1[v], tp1);
            u64 d;
            d = pk1(e0.x); m0 = fma2(d, wep0[0], m0); m1 = fma2(d, wep1[0], m1);
            d = pk1(e0.y); m0 = fma2(d, wep0[1], m0); m1 = fma2(d, wep1[1], m1);
            d = pk1(e0.z); m0 = fma2(d, wep0[2], m0); m1 = fma2(d, wep1[2], m1);
            d = pk1(e0.w); m0 = fma2(d, wep0[3], m0); m1 = fma2(d, wep1[3], m1);
            d = pk1(e1.x); m0 = fma2(d, wep0[4], m0); m1 = fma2(d, wep1[4], m1);
            d = pk1(e1.y); m0 = fma2(d, wep0[5], m0); m1 = fma2(d, wep1[5], m1);
            d = pk1(e1.z); m0 = fma2(d, wep0[6], m0); m1 = fma2(d, wep1[6], m1);
            d = pk1(e1.w); m0 = fma2(d, wep0[7], m0); m1 = fma2(d, wep1[7], m1);
            float av = (v == 0) ? a4.x : (v == 1) ? a4.y : (v == 2) ? a4.z : a4.w;
            float r00, r01, r10, r11;
            upk(m0, r00, r01); upk(m1, r10, r11);
            r00 = fmaxf(r00, 0.f); r01 = fmaxf(r01, 0.f);   // FMNMX -> alu pipe
            r10 = fmaxf(r10, 0.f); r11 = fmaxf(r11, 0.f);
            u64 a2 = pk1(av);
            ap0[v] = fma2(a2, pk(r00, r01), ap0[v]);
            ap1[v] = fma2(a2, pk(r10, r11), ap1[v]);
        }
    }

    // ---- reduction: across halves (shfl 16) then across 8 warps (smem) ----
    __shared__ float red[8][V_TILE][H_OUT];   // 8 KB
#pragma unroll
    for (int v = 0; v < V_TILE; v++) {
        float f0, f1, f2, f3;
        upk(ap0[v], f0, f1);
        upk(ap1[v], f2, f3);
        f0 += __shfl_xor_sync(0xffffffffu, f0, 16);
        f1 += __shfl_xor_sync(0xffffffffu, f1, 16);
        f2 += __shfl_xor_sync(0xffffffffu, f2, 16);
        f3 += __shfl_xor_sync(0xffffffffu, f3, 16);
        if (half == 0) {
            red[warp][v][hl]      = f0;
            red[warp][v][hl + 16] = f1;
            red[warp][v][hl + 32] = f2;
            red[warp][v][hl + 48] = f3;
        }
    }
    __syncthreads();
    const int v = tid >> 6;          // 0..3
    const int h = tid & 63;
    float s = 0.f;
#pragma unroll
    for (int k = 0; k < 8; k++) s += red[k][v][h];
    out[(size_t)(v0 + v) * H_OUT + h] = s;
}

// ---------- launch ----------
extern "C" void kernel_launch(void* const* d_in, const int* in_sizes, int n_in,
                              void* d_out, int out_size) {
    const int*   adj = (const int*)d_in[0];       // (1,1024,1024) int32
    const float* X   = (const float*)d_in[1];     // (1,1024,32)
    const float* E   = (const float*)d_in[2];     // (1,1024,1024,8)
    const float* W   = (const float*)d_in[3];     // (72,64)
    const float* b   = (const float*)d_in[4];     // (64,)
    float* out = (float*)d_out;                   // (1,1024,64)

    prep_st<<<N_NODES, H_OUT>>>(X, W, b);
    prep_a<<<N_NODES / V_TILE, 256>>>(adj);
    edgeconv_main<<<N_NODES / V_TILE, 256>>>(E, W, out);
}